// round 2
// baseline (speedup 1.0000x reference)
#include <cuda_runtime.h>
#include <stdint.h>

#define NN 100000
#define DD 512
#define SS 4

// Scratch for V = h_c @ W^T  (205 MB, static __device__ per harness rules)
__device__ float g_V[(size_t)NN * DD];

// ---------------------------------------------------------------------------
// Kernel 1: V[n,d] = sum_e W[d,e] * h_c[n,e]   (A=h_c [N,512], W [512,512])
// Tiled SIMT fp32 GEMM: BM=64, BN=64, BK=32, 256 threads, 4x4 microtile.
// ---------------------------------------------------------------------------
constexpr int BM = 64, BN = 64, BK = 32;

__global__ __launch_bounds__(256) void gemm_vwh(const float* __restrict__ A,
                                                const float* __restrict__ W) {
    __shared__ float As[BK][BM + 4];
    __shared__ float Ws[BK][BN + 4];

    const int bm = blockIdx.y * BM;
    const int bn = blockIdx.x * BN;
    const int tid = threadIdx.x;
    const int tx = tid & 15;   // N-dim thread coord (16 * 4 = 64)
    const int ty = tid >> 4;   // M-dim thread coord (16 * 4 = 64)

    float acc[4][4];
#pragma unroll
    for (int i = 0; i < 4; i++)
#pragma unroll
        for (int j = 0; j < 4; j++) acc[i][j] = 0.f;

    const int lr = tid >> 3;         // 0..31 (row within half-tile)
    const int lc = (tid & 7) << 2;   // 0,4,...,28 (float4 column)

    for (int kb = 0; kb < DD; kb += BK) {
#pragma unroll
        for (int p = 0; p < 2; p++) {
            const int r = lr + p * 32;
            const int gr = bm + r;
            float4 a = make_float4(0.f, 0.f, 0.f, 0.f);
            if (gr < NN) a = *(const float4*)&A[(size_t)gr * DD + kb + lc];
            As[lc + 0][r] = a.x; As[lc + 1][r] = a.y;
            As[lc + 2][r] = a.z; As[lc + 3][r] = a.w;
            const int gd = bn + r;
            const float4 w = *(const float4*)&W[(size_t)gd * DD + kb + lc];
            Ws[lc + 0][r] = w.x; Ws[lc + 1][r] = w.y;
            Ws[lc + 2][r] = w.z; Ws[lc + 3][r] = w.w;
        }
        __syncthreads();

#pragma unroll
        for (int k = 0; k < BK; k++) {
            const float4 av = *(const float4*)&As[k][ty << 2];
            const float4 wv = *(const float4*)&Ws[k][tx << 2];
            const float am[4] = {av.x, av.y, av.z, av.w};
            const float wm[4] = {wv.x, wv.y, wv.z, wv.w};
#pragma unroll
            for (int i = 0; i < 4; i++)
#pragma unroll
                for (int j = 0; j < 4; j++) acc[i][j] += am[i] * wm[j];
        }
        __syncthreads();
    }

#pragma unroll
    for (int i = 0; i < 4; i++) {
        const int gr = bm + (ty << 2) + i;
        if (gr < NN) {
            const float4 o = make_float4(acc[i][0], acc[i][1], acc[i][2], acc[i][3]);
            *(float4*)&g_V[(size_t)gr * DD + bn + (tx << 2)] = o;
        }
    }
}

// ---------------------------------------------------------------------------
// Kernel 2: one warp per row n. Computes
//   sc1[n]    = dot(h_pl[n], V[n]) + b
//   sc2[s][n] = dot(h_c[idx[s][n]], V[n]) + b   (written twice: s and s+S)
// NOTE: sample_list is int32 on device (JAX x64 disabled downcasts int64).
// ---------------------------------------------------------------------------
__global__ __launch_bounds__(256) void dots_kernel(const float* __restrict__ hc,
                                                   const float* __restrict__ hpl,
                                                   const int* __restrict__ samp,
                                                   const float* __restrict__ bptr,
                                                   float* __restrict__ out) {
    const int wid = (blockIdx.x * blockDim.x + threadIdx.x) >> 5;
    const int lane = threadIdx.x & 31;
    if (wid >= NN) return;
    const int n = wid;

    const float4* __restrict__ v = (const float4*)(g_V + (size_t)n * DD);
    const float4* __restrict__ p = (const float4*)(hpl + (size_t)n * DD);
    const float4* __restrict__ g0 = (const float4*)(hc + (size_t)samp[0 * NN + n] * DD);
    const float4* __restrict__ g1 = (const float4*)(hc + (size_t)samp[1 * NN + n] * DD);
    const float4* __restrict__ g2 = (const float4*)(hc + (size_t)samp[2 * NN + n] * DD);
    const float4* __restrict__ g3 = (const float4*)(hc + (size_t)samp[3 * NN + n] * DD);

    float a0 = 0.f, a1 = 0.f, a2 = 0.f, a3 = 0.f, a4 = 0.f;
#pragma unroll
    for (int c = lane; c < DD / 4; c += 32) {
        const float4 vv = v[c];
        float4 x;
        x = p[c];  a0 += vv.x * x.x + vv.y * x.y + vv.z * x.z + vv.w * x.w;
        x = g0[c]; a1 += vv.x * x.x + vv.y * x.y + vv.z * x.z + vv.w * x.w;
        x = g1[c]; a2 += vv.x * x.x + vv.y * x.y + vv.z * x.z + vv.w * x.w;
        x = g2[c]; a3 += vv.x * x.x + vv.y * x.y + vv.z * x.z + vv.w * x.w;
        x = g3[c]; a4 += vv.x * x.x + vv.y * x.y + vv.z * x.z + vv.w * x.w;
    }
#pragma unroll
    for (int off = 16; off > 0; off >>= 1) {
        a0 += __shfl_xor_sync(0xFFFFFFFFu, a0, off);
        a1 += __shfl_xor_sync(0xFFFFFFFFu, a1, off);
        a2 += __shfl_xor_sync(0xFFFFFFFFu, a2, off);
        a3 += __shfl_xor_sync(0xFFFFFFFFu, a3, off);
        a4 += __shfl_xor_sync(0xFFFFFFFFu, a4, off);
    }
    if (lane == 0) {
        const float b = bptr[0];
        out[n] = a0 + b;
        const float r1 = a1 + b, r2 = a2 + b, r3 = a3 + b, r4 = a4 + b;
        out[NN + 0 * NN + n] = r1;  out[NN + (SS + 0) * NN + n] = r1;
        out[NN + 1 * NN + n] = r2;  out[NN + (SS + 1) * NN + n] = r2;
        out[NN + 2 * NN + n] = r3;  out[NN + (SS + 2) * NN + n] = r3;
        out[NN + 3 * NN + n] = r4;  out[NN + (SS + 3) * NN + n] = r4;
    }
}

extern "C" void kernel_launch(void* const* d_in, const int* in_sizes, int n_in,
                              void* d_out, int out_size) {
    const float* h_c  = (const float*)d_in[0];      // [1, N, D]
    const float* h_pl = (const float*)d_in[1];      // [1, N, D]
    const int*   samp = (const int*)d_in[2];        // [S, N] int32 (JAX x64 off)
    const float* W    = (const float*)d_in[3];      // [1, D, D]
    const float* b    = (const float*)d_in[4];      // [1]
    float* out = (float*)d_out;                      // [1, N + 2*S*N]

    dim3 g1(DD / BN, (NN + BM - 1) / BM);
    gemm_vwh<<<g1, 256>>>(h_c, W);

    const int blocks = (NN * 32 + 255) / 256;
    dots_kernel<<<blocks, 256>>>(h_c, h_pl, samp, b, out);
}

// round 4
// speedup vs baseline: 2.2426x; 2.2426x over previous
#include <cuda_runtime.h>
#include <stdint.h>

#define NN 100000
#define DD 512
#define SS 4

// Scratch for V = h_c @ W^T (205 MB static __device__, per harness rules)
__device__ float g_V[(size_t)NN * DD];

// ---------------------------------------------------------------------------
// bf16 hi/lo split helpers: x = hi(x) + lo(x), each representable in bf16.
// pack two floats into one bf16x2 register.
// ---------------------------------------------------------------------------
__device__ __forceinline__ uint32_t pack_hi(float x, float y, float& hx, float& hy) {
    uint32_t r;
    asm("cvt.rn.bf16x2.f32 %0, %1, %2;" : "=r"(r) : "f"(y), "f"(x));
    hx = __uint_as_float((r & 0xFFFFu) << 16);
    hy = __uint_as_float(r & 0xFFFF0000u);
    return r;
}
__device__ __forceinline__ uint32_t pack_lo(float x, float y) {
    uint32_t r;
    asm("cvt.rn.bf16x2.f32 %0, %1, %2;" : "=r"(r) : "f"(y), "f"(x));
    return r;
}

__device__ __forceinline__ void mma16816(float c[4], const uint32_t a[4],
                                         uint32_t b0, uint32_t b1) {
    asm volatile(
        "mma.sync.aligned.m16n8k16.row.col.f32.bf16.bf16.f32 "
        "{%0,%1,%2,%3}, {%4,%5,%6,%7}, {%8,%9}, {%0,%1,%2,%3};"
        : "+f"(c[0]), "+f"(c[1]), "+f"(c[2]), "+f"(c[3])
        : "r"(a[0]), "r"(a[1]), "r"(a[2]), "r"(a[3]), "r"(b0), "r"(b1));
}

// ---------------------------------------------------------------------------
// GEMM: V[n,d] = sum_e h_c[n,e] * W[d,e]
// CTA tile 64(M) x 256(N), K chunks of 32. 8 warps, warp tile 64x32.
// 3-pass bf16 split: acc += Ahi*Bhi + Ahi*Blo + Alo*Bhi (fp32 accumulate).
// ---------------------------------------------------------------------------
constexpr int BM = 64, BN = 256, BK = 32;
constexpr int AST = BK + 4;   // padded row stride in halves (72B: conflict-free frag loads)

__global__ __launch_bounds__(256, 2) void gemm_mma(const float* __restrict__ A,
                                                   const float* __restrict__ W) {
    __shared__ __align__(16) uint16_t sAhi[BM][AST];
    __shared__ __align__(16) uint16_t sAlo[BM][AST];
    __shared__ __align__(16) uint16_t sBhi[BN][AST];
    __shared__ __align__(16) uint16_t sBlo[BN][AST];

    const int tid = threadIdx.x;
    const int wid = tid >> 5;
    const int lane = tid & 31;
    const int g = lane >> 2;        // 0..7
    const int t = lane & 3;         // 0..3
    const int bm = blockIdx.y * BM;
    const int bn = blockIdx.x * BN;

    float acc[4][4][4];             // [mtile][ntile][c0..c3]
#pragma unroll
    for (int i = 0; i < 4; i++)
#pragma unroll
        for (int j = 0; j < 4; j++)
#pragma unroll
            for (int q = 0; q < 4; q++) acc[i][j][q] = 0.f;

    for (int kb = 0; kb < DD; kb += BK) {
        // ---- load + split A chunk [64 x 32] : 4 float2 per thread ----
#pragma unroll
        for (int it = 0; it < 4; it++) {
            const int item = tid + it * 256;     // 0..1023
            const int row = item >> 4;           // 0..63
            const int c2 = item & 15;            // float2 col
            const int gr = bm + row;
            float2 f = make_float2(0.f, 0.f);
            if (gr < NN) f = *(const float2*)&A[(size_t)gr * DD + kb + c2 * 2];
            float hx, hy;
            const uint32_t hi = pack_hi(f.x, f.y, hx, hy);
            const uint32_t lo = pack_lo(f.x - hx, f.y - hy);
            *(uint32_t*)&sAhi[row][c2 * 2] = hi;
            *(uint32_t*)&sAlo[row][c2 * 2] = lo;
        }
        // ---- load + split B=W chunk [256 x 32] : 16 float2 per thread ----
#pragma unroll
        for (int it = 0; it < 16; it++) {
            const int item = tid + it * 256;     // 0..4095
            const int row = item >> 4;           // 0..255 (output dim d)
            const int c2 = item & 15;
            const float2 f = *(const float2*)&W[(size_t)(bn + row) * DD + kb + c2 * 2];
            float hx, hy;
            const uint32_t hi = pack_hi(f.x, f.y, hx, hy);
            const uint32_t lo = pack_lo(f.x - hx, f.y - hy);
            *(uint32_t*)&sBhi[row][c2 * 2] = hi;
            *(uint32_t*)&sBlo[row][c2 * 2] = lo;
        }
        __syncthreads();

        // ---- compute: 2 k-steps of 16 ----
#pragma unroll
        for (int s = 0; s < 2; s++) {
            const int kc = s * 16 + t * 2;
            uint32_t ah[4][4], al[4][4];
#pragma unroll
            for (int i = 0; i < 4; i++) {
                const int r0 = i * 16 + g;
                ah[i][0] = *(const uint32_t*)&sAhi[r0][kc];
                ah[i][1] = *(const uint32_t*)&sAhi[r0 + 8][kc];
                ah[i][2] = *(const uint32_t*)&sAhi[r0][kc + 8];
                ah[i][3] = *(const uint32_t*)&sAhi[r0 + 8][kc + 8];
                al[i][0] = *(const uint32_t*)&sAlo[r0][kc];
                al[i][1] = *(const uint32_t*)&sAlo[r0 + 8][kc];
                al[i][2] = *(const uint32_t*)&sAlo[r0][kc + 8];
                al[i][3] = *(const uint32_t*)&sAlo[r0 + 8][kc + 8];
            }
#pragma unroll
            for (int j = 0; j < 4; j++) {
                const int cn = wid * 32 + j * 8 + g;
                const uint32_t bh0 = *(const uint32_t*)&sBhi[cn][kc];
                const uint32_t bh1 = *(const uint32_t*)&sBhi[cn][kc + 8];
                const uint32_t bl0 = *(const uint32_t*)&sBlo[cn][kc];
                const uint32_t bl1 = *(const uint32_t*)&sBlo[cn][kc + 8];
#pragma unroll
                for (int i = 0; i < 4; i++) {
                    mma16816(acc[i][j], ah[i], bh0, bh1);
                    mma16816(acc[i][j], ah[i], bl0, bl1);
                    mma16816(acc[i][j], al[i], bh0, bh1);
                }
            }
        }
        __syncthreads();
    }

    // ---- epilogue: write V ----
#pragma unroll
    for (int i = 0; i < 4; i++) {
#pragma unroll
        for (int j = 0; j < 4; j++) {
            const int col = bn + wid * 32 + j * 8 + t * 2;
            const int r0 = bm + i * 16 + g;
            const int r1 = r0 + 8;
            if (r0 < NN)
                *(float2*)&g_V[(size_t)r0 * DD + col] =
                    make_float2(acc[i][j][0], acc[i][j][1]);
            if (r1 < NN)
                *(float2*)&g_V[(size_t)r1 * DD + col] =
                    make_float2(acc[i][j][2], acc[i][j][3]);
        }
    }
}

// ---------------------------------------------------------------------------
// Kernel 2: one warp per row n (unchanged; 84% DRAM, near roofline)
// ---------------------------------------------------------------------------
__global__ __launch_bounds__(256) void dots_kernel(const float* __restrict__ hc,
                                                   const float* __restrict__ hpl,
                                                   const int* __restrict__ samp,
                                                   const float* __restrict__ bptr,
                                                   float* __restrict__ out) {
    const int wid = (blockIdx.x * blockDim.x + threadIdx.x) >> 5;
    const int lane = threadIdx.x & 31;
    if (wid >= NN) return;
    const int n = wid;

    const float4* __restrict__ v = (const float4*)(g_V + (size_t)n * DD);
    const float4* __restrict__ p = (const float4*)(hpl + (size_t)n * DD);
    const float4* __restrict__ g0 = (const float4*)(hc + (size_t)samp[0 * NN + n] * DD);
    const float4* __restrict__ g1 = (const float4*)(hc + (size_t)samp[1 * NN + n] * DD);
    const float4* __restrict__ g2 = (const float4*)(hc + (size_t)samp[2 * NN + n] * DD);
    const float4* __restrict__ g3 = (const float4*)(hc + (size_t)samp[3 * NN + n] * DD);

    float a0 = 0.f, a1 = 0.f, a2 = 0.f, a3 = 0.f, a4 = 0.f;
#pragma unroll
    for (int c = lane; c < DD / 4; c += 32) {
        const float4 vv = v[c];
        float4 x;
        x = p[c];  a0 += vv.x * x.x + vv.y * x.y + vv.z * x.z + vv.w * x.w;
        x = g0[c]; a1 += vv.x * x.x + vv.y * x.y + vv.z * x.z + vv.w * x.w;
        x = g1[c]; a2 += vv.x * x.x + vv.y * x.y + vv.z * x.z + vv.w * x.w;
        x = g2[c]; a3 += vv.x * x.x + vv.y * x.y + vv.z * x.z + vv.w * x.w;
        x = g3[c]; a4 += vv.x * x.x + vv.y * x.y + vv.z * x.z + vv.w * x.w;
    }
#pragma unroll
    for (int off = 16; off > 0; off >>= 1) {
        a0 += __shfl_xor_sync(0xFFFFFFFFu, a0, off);
        a1 += __shfl_xor_sync(0xFFFFFFFFu, a1, off);
        a2 += __shfl_xor_sync(0xFFFFFFFFu, a2, off);
        a3 += __shfl_xor_sync(0xFFFFFFFFu, a3, off);
        a4 += __shfl_xor_sync(0xFFFFFFFFu, a4, off);
    }
    if (lane == 0) {
        const float b = bptr[0];
        out[n] = a0 + b;
        const float r1 = a1 + b, r2 = a2 + b, r3 = a3 + b, r4 = a4 + b;
        out[NN + 0 * NN + n] = r1;  out[NN + (SS + 0) * NN + n] = r1;
        out[NN + 1 * NN + n] = r2;  out[NN + (SS + 1) * NN + n] = r2;
        out[NN + 2 * NN + n] = r3;  out[NN + (SS + 2) * NN + n] = r3;
        out[NN + 3 * NN + n] = r4;  out[NN + (SS + 3) * NN + n] = r4;
    }
}

extern "C" void kernel_launch(void* const* d_in, const int* in_sizes, int n_in,
                              void* d_out, int out_size) {
    const float* h_c  = (const float*)d_in[0];      // [1, N, D]
    const float* h_pl = (const float*)d_in[1];      // [1, N, D]
    const int*   samp = (const int*)d_in[2];        // [S, N] int32
    const float* W    = (const float*)d_in[3];      // [1, D, D]
    const float* b    = (const float*)d_in[4];      // [1]
    float* out = (float*)d_out;

    dim3 grid(DD / BN, (NN + BM - 1) / BM);          // (2, 1563)
    gemm_mma<<<grid, 256>>>(h_c, W);

    const int blocks = (NN * 32 + 255) / 256;
    dots_kernel<<<blocks, 256>>>(h_c, h_pl, samp, b, out);
}

// round 5
// speedup vs baseline: 2.3440x; 1.0452x over previous
#include <cuda_runtime.h>
#include <stdint.h>

#define NN 100000
#define DD 512
#define SS 4

// Static device scratch (no allocs allowed)
__device__ float    g_V[(size_t)NN * DD];     // V = h_c @ W^T
__device__ uint16_t g_Whi[DD * DD];           // W split, bf16 hi
__device__ uint16_t g_Wlo[DD * DD];           // W split, bf16 lo

// ---------------------------------------------------------------------------
// helpers
// ---------------------------------------------------------------------------
__device__ __forceinline__ uint32_t smem_u32(const void* p) {
    uint32_t a;
    asm("{ .reg .u64 t; cvta.to.shared.u64 t, %1; cvt.u32.u64 %0, t; }"
        : "=r"(a) : "l"(p));
    return a;
}
__device__ __forceinline__ uint32_t pack_hi(float x, float y, float& hx, float& hy) {
    uint32_t r;
    asm("cvt.rn.bf16x2.f32 %0, %1, %2;" : "=r"(r) : "f"(y), "f"(x));
    hx = __uint_as_float((r & 0xFFFFu) << 16);
    hy = __uint_as_float(r & 0xFFFF0000u);
    return r;
}
__device__ __forceinline__ uint32_t pack_lo(float x, float y) {
    uint32_t r;
    asm("cvt.rn.bf16x2.f32 %0, %1, %2;" : "=r"(r) : "f"(y), "f"(x));
    return r;
}
__device__ __forceinline__ void mma16816(float c[4], const uint32_t a[4],
                                         uint32_t b0, uint32_t b1) {
    asm volatile(
        "mma.sync.aligned.m16n8k16.row.col.f32.bf16.bf16.f32 "
        "{%0,%1,%2,%3}, {%4,%5,%6,%7}, {%8,%9}, {%0,%1,%2,%3};"
        : "+f"(c[0]), "+f"(c[1]), "+f"(c[2]), "+f"(c[3])
        : "r"(a[0]), "r"(a[1]), "r"(a[2]), "r"(a[3]), "r"(b0), "r"(b1));
}
__device__ __forceinline__ void cp16(uint32_t dst, const void* src) {
    asm volatile("cp.async.cg.shared.global [%0], [%1], 16;"
                 :: "r"(dst), "l"(src));
}
__device__ __forceinline__ void cp_commit() {
    asm volatile("cp.async.commit_group;" ::: "memory");
}
__device__ __forceinline__ void cp_wait_all() {
    asm volatile("cp.async.wait_group 0;" ::: "memory");
}

// ---------------------------------------------------------------------------
// Kernel 0: split W [512x512] fp32 -> bf16 hi/lo (runs once per launch, ~5us)
// ---------------------------------------------------------------------------
__global__ __launch_bounds__(256) void split_w(const float* __restrict__ W) {
    const int i = blockIdx.x * 256 + threadIdx.x;   // over 131072 float2
    const float2 f = ((const float2*)W)[i];
    float hx, hy;
    const uint32_t hi = pack_hi(f.x, f.y, hx, hy);
    const uint32_t lo = pack_lo(f.x - hx, f.y - hy);
    ((uint32_t*)g_Whi)[i] = hi;
    ((uint32_t*)g_Wlo)[i] = lo;
}

// ---------------------------------------------------------------------------
// GEMM: V[n,d] = sum_e h_c[n,e] * W[d,e]
// CTA: 64(M) x 512(N), 512 threads (16 warps, warp tile 64x32), K chunks of 32.
// cp.async double-buffered B (pre-split bf16), register-prefetched A.
// Smem rows padded to 80B -> conflict-free fragment LDS.
// ---------------------------------------------------------------------------
constexpr int BM = 64, BN = 512, BK = 32;
constexpr int NCH = DD / BK;           // 16 chunks
constexpr int RS = 80;                 // row stride bytes (32 halves = 64B + 16B pad)
// smem layout (bytes)
constexpr int A_HI0 = 0;                         // 64*80 per buf
constexpr int A_LO0 = 2 * BM * RS;               // 10240
constexpr int B_HI0 = 4 * BM * RS;               // 20480, 512*80 per buf
constexpr int B_LO0 = B_HI0 + 2 * BN * RS;       // 102400
constexpr int SMEM_BYTES = B_LO0 + 2 * BN * RS;  // 184320
#define A_HI(b) (A_HI0 + (b) * BM * RS)
#define A_LO(b) (A_LO0 + (b) * BM * RS)
#define B_HI(b) (B_HI0 + (b) * BN * RS)
#define B_LO(b) (B_LO0 + (b) * BN * RS)

__global__ __launch_bounds__(512, 1) void gemm_mma(const float* __restrict__ A) {
    extern __shared__ char smem[];
    const uint32_t sb = smem_u32(smem);
    const int tid = threadIdx.x;
    const int wid = tid >> 5;
    const int lane = tid & 31;
    const int g = lane >> 2;    // 0..7
    const int t = lane & 3;     // 0..3
    const int bm = blockIdx.x * BM;

    float acc[4][4][4];
#pragma unroll
    for (int i = 0; i < 4; i++)
#pragma unroll
        for (int j = 0; j < 4; j++)
#pragma unroll
            for (int q = 0; q < 4; q++) acc[i][j][q] = 0.f;

    // per-thread load coords
    const int a_row0 = tid >> 4;              // item = tid + it*512, row = item>>4
    const int a_c2 = tid & 15;
    const int b_row0 = tid >> 2;              // item>>2
    const int b_seg = tid & 3;

    float2 areg[2];

    // ---- helpers as lambdas ----
    auto loadA = [&](int kc) {
#pragma unroll
        for (int it = 0; it < 2; it++) {
            const int row = a_row0 + it * 32;
            const int gr = bm + row;
            areg[it] = make_float2(0.f, 0.f);
            if (gr < NN)
                areg[it] = *(const float2*)&A[(size_t)gr * DD + kc * BK + a_c2 * 2];
        }
    };
    auto storeA = [&](int buf) {
#pragma unroll
        for (int it = 0; it < 2; it++) {
            const int row = a_row0 + it * 32;
            float hx, hy;
            const uint32_t hi = pack_hi(areg[it].x, areg[it].y, hx, hy);
            const uint32_t lo = pack_lo(areg[it].x - hx, areg[it].y - hy);
            *(uint32_t*)(smem + A_HI(buf) + row * RS + a_c2 * 4) = hi;
            *(uint32_t*)(smem + A_LO(buf) + row * RS + a_c2 * 4) = lo;
        }
    };
    auto issueB = [&](int kc, int buf) {
#pragma unroll
        for (int it = 0; it < 4; it++) {
            const int row = b_row0 + it * 128;
            const size_t gsrc = (size_t)row * DD + kc * BK + b_seg * 8;
            const uint32_t doff = row * RS + b_seg * 16;
            cp16(sb + B_HI(buf) + doff, g_Whi + gsrc);
            cp16(sb + B_LO(buf) + doff, g_Wlo + gsrc);
        }
        cp_commit();
    };

    // ---- prologue: chunk 0 ----
    loadA(0);
    issueB(0, 0);
    storeA(0);
    cp_wait_all();
    __syncthreads();

    for (int kc = 0; kc < NCH; kc++) {
        const int cur = kc & 1;
        const int nxt = cur ^ 1;
        if (kc + 1 < NCH) {
            loadA(kc + 1);
            issueB(kc + 1, nxt);
        }

        // ---- compute chunk kc from buf cur ----
#pragma unroll
        for (int s = 0; s < 2; s++) {
            const int koff = s * 32 + t * 4;   // byte offset of k position
            uint32_t ah[4][4], al[4][4];
#pragma unroll
            for (int i = 0; i < 4; i++) {
                const int r0 = i * 16 + g;
                const char* pa0 = smem + A_HI(cur) + r0 * RS + koff;
                const char* pa1 = smem + A_HI(cur) + (r0 + 8) * RS + koff;
                const char* pl0 = smem + A_LO(cur) + r0 * RS + koff;
                const char* pl1 = smem + A_LO(cur) + (r0 + 8) * RS + koff;
                ah[i][0] = *(const uint32_t*)pa0;
                ah[i][1] = *(const uint32_t*)pa1;
                ah[i][2] = *(const uint32_t*)(pa0 + 16);
                ah[i][3] = *(const uint32_t*)(pa1 + 16);
                al[i][0] = *(const uint32_t*)pl0;
                al[i][1] = *(const uint32_t*)pl1;
                al[i][2] = *(const uint32_t*)(pl0 + 16);
                al[i][3] = *(const uint32_t*)(pl1 + 16);
            }
#pragma unroll
            for (int j = 0; j < 4; j++) {
                const int cn = wid * 32 + j * 8 + g;
                const char* pb = smem + B_HI(cur) + cn * RS + koff;
                const char* pq = smem + B_LO(cur) + cn * RS + koff;
                const uint32_t bh0 = *(const uint32_t*)pb;
                const uint32_t bh1 = *(const uint32_t*)(pb + 16);
                const uint32_t bl0 = *(const uint32_t*)pq;
                const uint32_t bl1 = *(const uint32_t*)(pq + 16);
#pragma unroll
                for (int i = 0; i < 4; i++) {
                    mma16816(acc[i][j], ah[i], bh0, bh1);
                    mma16816(acc[i][j], ah[i], bl0, bl1);
                    mma16816(acc[i][j], al[i], bh0, bh1);
                }
            }
        }

        if (kc + 1 < NCH) storeA(nxt);
        cp_wait_all();
        __syncthreads();
    }

    // ---- epilogue: write V ----
#pragma unroll
    for (int i = 0; i < 4; i++) {
#pragma unroll
        for (int j = 0; j < 4; j++) {
            const int col = wid * 32 + j * 8 + t * 2;
            const int r0 = bm + i * 16 + g;
            const int r1 = r0 + 8;
            if (r0 < NN)
                *(float2*)&g_V[(size_t)r0 * DD + col] =
                    make_float2(acc[i][j][0], acc[i][j][1]);
            if (r1 < NN)
                *(float2*)&g_V[(size_t)r1 * DD + col] =
                    make_float2(acc[i][j][2], acc[i][j][3]);
        }
    }
}

// ---------------------------------------------------------------------------
// Kernel 2: one warp per row n (unchanged; 83% DRAM, near roofline)
// ---------------------------------------------------------------------------
__global__ __launch_bounds__(256) void dots_kernel(const float* __restrict__ hc,
                                                   const float* __restrict__ hpl,
                                                   const int* __restrict__ samp,
                                                   const float* __restrict__ bptr,
                                                   float* __restrict__ out) {
    const int wid = (blockIdx.x * blockDim.x + threadIdx.x) >> 5;
    const int lane = threadIdx.x & 31;
    if (wid >= NN) return;
    const int n = wid;

    const float4* __restrict__ v = (const float4*)(g_V + (size_t)n * DD);
    const float4* __restrict__ p = (const float4*)(hpl + (size_t)n * DD);
    const float4* __restrict__ g0 = (const float4*)(hc + (size_t)samp[0 * NN + n] * DD);
    const float4* __restrict__ g1 = (const float4*)(hc + (size_t)samp[1 * NN + n] * DD);
    const float4* __restrict__ g2 = (const float4*)(hc + (size_t)samp[2 * NN + n] * DD);
    const float4* __restrict__ g3 = (const float4*)(hc + (size_t)samp[3 * NN + n] * DD);

    float a0 = 0.f, a1 = 0.f, a2 = 0.f, a3 = 0.f, a4 = 0.f;
#pragma unroll
    for (int c = lane; c < DD / 4; c += 32) {
        const float4 vv = v[c];
        float4 x;
        x = p[c];  a0 += vv.x * x.x + vv.y * x.y + vv.z * x.z + vv.w * x.w;
        x = g0[c]; a1 += vv.x * x.x + vv.y * x.y + vv.z * x.z + vv.w * x.w;
        x = g1[c]; a2 += vv.x * x.x + vv.y * x.y + vv.z * x.z + vv.w * x.w;
        x = g2[c]; a3 += vv.x * x.x + vv.y * x.y + vv.z * x.z + vv.w * x.w;
        x = g3[c]; a4 += vv.x * x.x + vv.y * x.y + vv.z * x.z + vv.w * x.w;
    }
#pragma unroll
    for (int off = 16; off > 0; off >>= 1) {
        a0 += __shfl_xor_sync(0xFFFFFFFFu, a0, off);
        a1 += __shfl_xor_sync(0xFFFFFFFFu, a1, off);
        a2 += __shfl_xor_sync(0xFFFFFFFFu, a2, off);
        a3 += __shfl_xor_sync(0xFFFFFFFFu, a3, off);
        a4 += __shfl_xor_sync(0xFFFFFFFFu, a4, off);
    }
    if (lane == 0) {
        const float b = bptr[0];
        out[n] = a0 + b;
        const float r1 = a1 + b, r2 = a2 + b, r3 = a3 + b, r4 = a4 + b;
        out[NN + 0 * NN + n] = r1;  out[NN + (SS + 0) * NN + n] = r1;
        out[NN + 1 * NN + n] = r2;  out[NN + (SS + 1) * NN + n] = r2;
        out[NN + 2 * NN + n] = r3;  out[NN + (SS + 2) * NN + n] = r3;
        out[NN + 3 * NN + n] = r4;  out[NN + (SS + 3) * NN + n] = r4;
    }
}

extern "C" void kernel_launch(void* const* d_in, const int* in_sizes, int n_in,
                              void* d_out, int out_size) {
    const float* h_c  = (const float*)d_in[0];
    const float* h_pl = (const float*)d_in[1];
    const int*   samp = (const int*)d_in[2];
    const float* W    = (const float*)d_in[3];
    const float* b    = (const float*)d_in[4];
    float* out = (float*)d_out;

    split_w<<<512, 256>>>(W);

    static int smem_set = 0;
    if (!smem_set) {
        cudaFuncSetAttribute(gemm_mma, cudaFuncAttributeMaxDynamicSharedMemorySize,
                             SMEM_BYTES);
        smem_set = 1;
    }
    const int grid = (NN + BM - 1) / BM;   // 1563
    gemm_mma<<<grid, 512, SMEM_BYTES>>>(h_c);

    const int blocks = (NN * 32 + 255) / 256;
    dots_kernel<<<blocks, 256>>>(h_c, h_pl, samp, b, out);
}

// round 6
// speedup vs baseline: 2.5069x; 1.0695x over previous
#include <cuda_runtime.h>
#include <stdint.h>

#define NN 100000
#define DD 512
#define SS 4

// Static device scratch (no allocs allowed)
__device__ uint16_t g_Whi[DD * DD];           // W split, bf16 hi
__device__ uint16_t g_Wlo[DD * DD];           // W split, bf16 lo

// ---------------------------------------------------------------------------
// helpers
// ---------------------------------------------------------------------------
__device__ __forceinline__ uint32_t smem_u32(const void* p) {
    uint32_t a;
    asm("{ .reg .u64 t; cvta.to.shared.u64 t, %1; cvt.u32.u64 %0, t; }"
        : "=r"(a) : "l"(p));
    return a;
}
__device__ __forceinline__ uint32_t pack_hi(float x, float y, float& hx, float& hy) {
    uint32_t r;
    asm("cvt.rn.bf16x2.f32 %0, %1, %2;" : "=r"(r) : "f"(y), "f"(x));
    hx = __uint_as_float((r & 0xFFFFu) << 16);
    hy = __uint_as_float(r & 0xFFFF0000u);
    return r;
}
__device__ __forceinline__ uint32_t pack_lo(float x, float y) {
    uint32_t r;
    asm("cvt.rn.bf16x2.f32 %0, %1, %2;" : "=r"(r) : "f"(y), "f"(x));
    return r;
}
__device__ __forceinline__ void mma16816(float c[4], const uint32_t a[4],
                                         uint32_t b0, uint32_t b1) {
    asm volatile(
        "mma.sync.aligned.m16n8k16.row.col.f32.bf16.bf16.f32 "
        "{%0,%1,%2,%3}, {%4,%5,%6,%7}, {%8,%9}, {%0,%1,%2,%3};"
        : "+f"(c[0]), "+f"(c[1]), "+f"(c[2]), "+f"(c[3])
        : "r"(a[0]), "r"(a[1]), "r"(a[2]), "r"(a[3]), "r"(b0), "r"(b1));
}
__device__ __forceinline__ void cp16(uint32_t dst, const void* src) {
    asm volatile("cp.async.cg.shared.global [%0], [%1], 16;"
                 :: "r"(dst), "l"(src));
}
__device__ __forceinline__ void cp_commit() {
    asm volatile("cp.async.commit_group;" ::: "memory");
}
__device__ __forceinline__ void cp_wait_all() {
    asm volatile("cp.async.wait_group 0;" ::: "memory");
}

// ---------------------------------------------------------------------------
// Kernel 0: split W [512x512] fp32 -> bf16 hi/lo (once per launch, ~5us)
// ---------------------------------------------------------------------------
__global__ __launch_bounds__(256) void split_w(const float* __restrict__ W) {
    const int i = blockIdx.x * 256 + threadIdx.x;   // over 131072 float2
    const float2 f = ((const float2*)W)[i];
    float hx, hy;
    const uint32_t hi = pack_hi(f.x, f.y, hx, hy);
    const uint32_t lo = pack_lo(f.x - hx, f.y - hy);
    ((uint32_t*)g_Whi)[i] = hi;
    ((uint32_t*)g_Wlo)[i] = lo;
}

// ---------------------------------------------------------------------------
// Fused GEMM + dots.
// Mainloop: V_tile[64 x 512] = A_tile[64 x 512] @ W^T via mma.sync bf16 3-pass.
// Epilogue: stage V_tile in smem, each warp computes the 5 bilinear dots for
// 4 rows (h_pl + 4 gathered h_c rows from gmem), scatters 9 outputs.
// ---------------------------------------------------------------------------
constexpr int BM = 64, BN = 512, BK = 32;
constexpr int NCH = DD / BK;           // 16 chunks
constexpr int RS = 80;                 // smem row stride bytes (conflict-free)
constexpr int A_HI0 = 0;
constexpr int A_LO0 = 2 * BM * RS;               // 10240
constexpr int B_HI0 = 4 * BM * RS;               // 20480
constexpr int B_LO0 = B_HI0 + 2 * BN * RS;       // 102400
constexpr int MAIN_BYTES = B_LO0 + 2 * BN * RS;  // 184320
constexpr int VST = 516;                         // V staging stride (words)
constexpr int V_BYTES = BM * VST * 4;            // 132096
constexpr int SMEM_BYTES = MAIN_BYTES > V_BYTES ? MAIN_BYTES : V_BYTES;
#define A_HI(b) (A_HI0 + (b) * BM * RS)
#define A_LO(b) (A_LO0 + (b) * BM * RS)
#define B_HI(b) (B_HI0 + (b) * BN * RS)
#define B_LO(b) (B_LO0 + (b) * BN * RS)

__global__ __launch_bounds__(512, 1) void gemm_fused(const float* __restrict__ A,
                                                     const float* __restrict__ hpl,
                                                     const int* __restrict__ samp,
                                                     const float* __restrict__ bptr,
                                                     float* __restrict__ out) {
    extern __shared__ char smem[];
    const uint32_t sb = smem_u32(smem);
    const int tid = threadIdx.x;
    const int wid = tid >> 5;
    const int lane = tid & 31;
    const int g = lane >> 2;    // 0..7
    const int t = lane & 3;     // 0..3
    const int bm = blockIdx.x * BM;

    float acc[4][4][4];
#pragma unroll
    for (int i = 0; i < 4; i++)
#pragma unroll
        for (int j = 0; j < 4; j++)
#pragma unroll
            for (int q = 0; q < 4; q++) acc[i][j][q] = 0.f;

    const int a_row0 = tid >> 4;
    const int a_c2 = tid & 15;
    const int b_row0 = tid >> 2;
    const int b_seg = tid & 3;

    float2 areg[2];

    auto loadA = [&](int kc) {
#pragma unroll
        for (int it = 0; it < 2; it++) {
            const int row = a_row0 + it * 32;
            const int gr = bm + row;
            areg[it] = make_float2(0.f, 0.f);
            if (gr < NN)
                areg[it] = *(const float2*)&A[(size_t)gr * DD + kc * BK + a_c2 * 2];
        }
    };
    auto storeA = [&](int buf) {
#pragma unroll
        for (int it = 0; it < 2; it++) {
            const int row = a_row0 + it * 32;
            float hx, hy;
            const uint32_t hi = pack_hi(areg[it].x, areg[it].y, hx, hy);
            const uint32_t lo = pack_lo(areg[it].x - hx, areg[it].y - hy);
            *(uint32_t*)(smem + A_HI(buf) + row * RS + a_c2 * 4) = hi;
            *(uint32_t*)(smem + A_LO(buf) + row * RS + a_c2 * 4) = lo;
        }
    };
    auto issueB = [&](int kc, int buf) {
#pragma unroll
        for (int it = 0; it < 4; it++) {
            const int row = b_row0 + it * 128;
            const size_t gsrc = (size_t)row * DD + kc * BK + b_seg * 8;
            const uint32_t doff = row * RS + b_seg * 16;
            cp16(sb + B_HI(buf) + doff, g_Whi + gsrc);
            cp16(sb + B_LO(buf) + doff, g_Wlo + gsrc);
        }
        cp_commit();
    };

    loadA(0);
    issueB(0, 0);
    storeA(0);
    cp_wait_all();
    __syncthreads();

    for (int kc = 0; kc < NCH; kc++) {
        const int cur = kc & 1;
        const int nxt = cur ^ 1;
        if (kc + 1 < NCH) {
            loadA(kc + 1);
            issueB(kc + 1, nxt);
        }

#pragma unroll
        for (int s = 0; s < 2; s++) {
            const int koff = s * 32 + t * 4;
            uint32_t ah[4][4], al[4][4];
#pragma unroll
            for (int i = 0; i < 4; i++) {
                const int r0 = i * 16 + g;
                const char* pa0 = smem + A_HI(cur) + r0 * RS + koff;
                const char* pa1 = smem + A_HI(cur) + (r0 + 8) * RS + koff;
                const char* pl0 = smem + A_LO(cur) + r0 * RS + koff;
                const char* pl1 = smem + A_LO(cur) + (r0 + 8) * RS + koff;
                ah[i][0] = *(const uint32_t*)pa0;
                ah[i][1] = *(const uint32_t*)pa1;
                ah[i][2] = *(const uint32_t*)(pa0 + 16);
                ah[i][3] = *(const uint32_t*)(pa1 + 16);
                al[i][0] = *(const uint32_t*)pl0;
                al[i][1] = *(const uint32_t*)pl1;
                al[i][2] = *(const uint32_t*)(pl0 + 16);
                al[i][3] = *(const uint32_t*)(pl1 + 16);
            }
#pragma unroll
            for (int j = 0; j < 4; j++) {
                const int cn = wid * 32 + j * 8 + g;
                const char* pb = smem + B_HI(cur) + cn * RS + koff;
                const char* pq = smem + B_LO(cur) + cn * RS + koff;
                const uint32_t bh0 = *(const uint32_t*)pb;
                const uint32_t bh1 = *(const uint32_t*)(pb + 16);
                const uint32_t bl0 = *(const uint32_t*)pq;
                const uint32_t bl1 = *(const uint32_t*)(pq + 16);
#pragma unroll
                for (int i = 0; i < 4; i++) {
                    mma16816(acc[i][j], ah[i], bh0, bh1);
                    mma16816(acc[i][j], ah[i], bl0, bl1);
                    mma16816(acc[i][j], al[i], bh0, bh1);
                }
            }
        }

        if (kc + 1 < NCH) storeA(nxt);
        cp_wait_all();
        __syncthreads();
    }

    // ---- stage V tile [64 x 512] into smem (stride 516: conflict-free) ----
    float* sV = (float*)smem;
#pragma unroll
    for (int i = 0; i < 4; i++) {
#pragma unroll
        for (int j = 0; j < 4; j++) {
            const int col = wid * 32 + j * 8 + t * 2;
            const int r0 = i * 16 + g;
            const int r1 = r0 + 8;
            sV[r0 * VST + col] = acc[i][j][0];
            sV[r0 * VST + col + 1] = acc[i][j][1];
            sV[r1 * VST + col] = acc[i][j][2];
            sV[r1 * VST + col + 1] = acc[i][j][3];
        }
    }
    __syncthreads();

    // ---- dots: warp wid handles rows wid*4 .. wid*4+3 of this tile ----
    const float bconst = bptr[0];
#pragma unroll
    for (int rr = 0; rr < 4; rr++) {
        const int row = wid * 4 + rr;
        const int n = bm + row;
        if (n >= NN) break;

        const float4* __restrict__ v = (const float4*)(sV + row * VST);
        const float4* __restrict__ p = (const float4*)(hpl + (size_t)n * DD);
        const float4* __restrict__ g0 = (const float4*)(A + (size_t)samp[0 * NN + n] * DD);
        const float4* __restrict__ g1 = (const float4*)(A + (size_t)samp[1 * NN + n] * DD);
        const float4* __restrict__ g2 = (const float4*)(A + (size_t)samp[2 * NN + n] * DD);
        const float4* __restrict__ g3 = (const float4*)(A + (size_t)samp[3 * NN + n] * DD);

        float a0 = 0.f, a1 = 0.f, a2 = 0.f, a3 = 0.f, a4 = 0.f;
#pragma unroll
        for (int c = lane; c < DD / 4; c += 32) {
            const float4 vv = v[c];
            float4 x;
            x = p[c];  a0 += vv.x * x.x + vv.y * x.y + vv.z * x.z + vv.w * x.w;
            x = g0[c]; a1 += vv.x * x.x + vv.y * x.y + vv.z * x.z + vv.w * x.w;
            x = g1[c]; a2 += vv.x * x.x + vv.y * x.y + vv.z * x.z + vv.w * x.w;
            x = g2[c]; a3 += vv.x * x.x + vv.y * x.y + vv.z * x.z + vv.w * x.w;
            x = g3[c]; a4 += vv.x * x.x + vv.y * x.y + vv.z * x.z + vv.w * x.w;
        }
#pragma unroll
        for (int off = 16; off > 0; off >>= 1) {
            a0 += __shfl_xor_sync(0xFFFFFFFFu, a0, off);
            a1 += __shfl_xor_sync(0xFFFFFFFFu, a1, off);
            a2 += __shfl_xor_sync(0xFFFFFFFFu, a2, off);
            a3 += __shfl_xor_sync(0xFFFFFFFFu, a3, off);
            a4 += __shfl_xor_sync(0xFFFFFFFFu, a4, off);
        }
        if (lane == 0) {
            out[n] = a0 + bconst;
            const float r1 = a1 + bconst, r2 = a2 + bconst;
            const float r3 = a3 + bconst, r4 = a4 + bconst;
            out[NN + 0 * NN + n] = r1;  out[NN + (SS + 0) * NN + n] = r1;
            out[NN + 1 * NN + n] = r2;  out[NN + (SS + 1) * NN + n] = r2;
            out[NN + 2 * NN + n] = r3;  out[NN + (SS + 2) * NN + n] = r3;
            out[NN + 3 * NN + n] = r4;  out[NN + (SS + 3) * NN + n] = r4;
        }
    }
}

extern "C" void kernel_launch(void* const* d_in, const int* in_sizes, int n_in,
                              void* d_out, int out_size) {
    const float* h_c  = (const float*)d_in[0];
    const float* h_pl = (const float*)d_in[1];
    const int*   samp = (const int*)d_in[2];
    const float* W    = (const float*)d_in[3];
    const float* b    = (const float*)d_in[4];
    float* out = (float*)d_out;

    split_w<<<512, 256>>>(W);

    static int smem_set = 0;
    if (!smem_set) {
        cudaFuncSetAttribute(gemm_fused, cudaFuncAttributeMaxDynamicSharedMemorySize,
                             SMEM_BYTES);
        smem_set = 1;
    }
    const int grid = (NN + BM - 1) / BM;   // 1563
    gemm_fused<<<grid, 512, SMEM_BYTES>>>(h_c, h_pl, samp, b, out);
}

// round 7
// speedup vs baseline: 2.6812x; 1.0695x over previous
#include <cuda_runtime.h>
#include <stdint.h>

#define NN 100000
#define DD 512
#define SS 4

// Static device scratch (no allocs allowed)
__device__ uint16_t g_Whi[DD * DD];           // W split, bf16 hi
__device__ uint16_t g_Wlo[DD * DD];           // W split, bf16 lo

// ---------------------------------------------------------------------------
// helpers
// ---------------------------------------------------------------------------
__device__ __forceinline__ uint32_t smem_u32(const void* p) {
    uint32_t a;
    asm("{ .reg .u64 t; cvta.to.shared.u64 t, %1; cvt.u32.u64 %0, t; }"
        : "=r"(a) : "l"(p));
    return a;
}
__device__ __forceinline__ uint32_t pack_hi(float x, float y, float& hx, float& hy) {
    uint32_t r;
    asm("cvt.rn.bf16x2.f32 %0, %1, %2;" : "=r"(r) : "f"(y), "f"(x));
    hx = __uint_as_float((r & 0xFFFFu) << 16);
    hy = __uint_as_float(r & 0xFFFF0000u);
    return r;
}
__device__ __forceinline__ uint32_t pack_lo(float x, float y) {
    uint32_t r;
    asm("cvt.rn.bf16x2.f32 %0, %1, %2;" : "=r"(r) : "f"(y), "f"(x));
    return r;
}
__device__ __forceinline__ void mma16816(float c[4], const uint32_t a[4],
                                         uint32_t b0, uint32_t b1) {
    asm volatile(
        "mma.sync.aligned.m16n8k16.row.col.f32.bf16.bf16.f32 "
        "{%0,%1,%2,%3}, {%4,%5,%6,%7}, {%8,%9}, {%0,%1,%2,%3};"
        : "+f"(c[0]), "+f"(c[1]), "+f"(c[2]), "+f"(c[3])
        : "r"(a[0]), "r"(a[1]), "r"(a[2]), "r"(a[3]), "r"(b0), "r"(b1));
}
__device__ __forceinline__ void ldm_x4(uint32_t addr, uint32_t& r0, uint32_t& r1,
                                       uint32_t& r2, uint32_t& r3) {
    asm volatile("ldmatrix.sync.aligned.m8n8.x4.shared.b16 {%0,%1,%2,%3}, [%4];"
                 : "=r"(r0), "=r"(r1), "=r"(r2), "=r"(r3) : "r"(addr));
}
__device__ __forceinline__ void cp16(uint32_t dst, const void* src) {
    asm volatile("cp.async.cg.shared.global [%0], [%1], 16;"
                 :: "r"(dst), "l"(src));
}
__device__ __forceinline__ void cp_commit() {
    asm volatile("cp.async.commit_group;" ::: "memory");
}
__device__ __forceinline__ void cp_wait_all() {
    asm volatile("cp.async.wait_group 0;" ::: "memory");
}

// ---------------------------------------------------------------------------
// Kernel 0: split W [512x512] fp32 -> bf16 hi/lo (once per launch, ~5us)
// ---------------------------------------------------------------------------
__global__ __launch_bounds__(256) void split_w(const float* __restrict__ W) {
    const int i = blockIdx.x * 256 + threadIdx.x;   // over 131072 float2
    const float2 f = ((const float2*)W)[i];
    float hx, hy;
    const uint32_t hi = pack_hi(f.x, f.y, hx, hy);
    const uint32_t lo = pack_lo(f.x - hx, f.y - hy);
    ((uint32_t*)g_Whi)[i] = hi;
    ((uint32_t*)g_Wlo)[i] = lo;
}

// ---------------------------------------------------------------------------
// Fused GEMM + dots. Mainloop fragments via ldmatrix.x4.
// ---------------------------------------------------------------------------
constexpr int BM = 64, BN = 512, BK = 32;
constexpr int NCH = DD / BK;           // 16 chunks
constexpr int RS = 80;                 // smem row stride bytes
constexpr int A_HI0 = 0;
constexpr int A_LO0 = 2 * BM * RS;               // 10240
constexpr int B_HI0 = 4 * BM * RS;               // 20480
constexpr int B_LO0 = B_HI0 + 2 * BN * RS;       // 102400
constexpr int MAIN_BYTES = B_LO0 + 2 * BN * RS;  // 184320
constexpr int VST = 516;                         // V staging stride (words)
constexpr int V_BYTES = BM * VST * 4;            // 132096
constexpr int SMEM_BYTES = MAIN_BYTES > V_BYTES ? MAIN_BYTES : V_BYTES;
#define A_HI(b) (A_HI0 + (b) * BM * RS)
#define A_LO(b) (A_LO0 + (b) * BM * RS)
#define B_HI(b) (B_HI0 + (b) * BN * RS)
#define B_LO(b) (B_LO0 + (b) * BN * RS)

__global__ __launch_bounds__(512, 1) void gemm_fused(const float* __restrict__ A,
                                                     const float* __restrict__ hpl,
                                                     const int* __restrict__ samp,
                                                     const float* __restrict__ bptr,
                                                     float* __restrict__ out) {
    extern __shared__ char smem[];
    const uint32_t sb = smem_u32(smem);
    const int tid = threadIdx.x;
    const int wid = tid >> 5;
    const int lane = tid & 31;
    const int t = lane & 3;
    const int bm = blockIdx.x * BM;

    float acc[4][4][4];
#pragma unroll
    for (int i = 0; i < 4; i++)
#pragma unroll
        for (int j = 0; j < 4; j++)
#pragma unroll
            for (int q = 0; q < 4; q++) acc[i][j][q] = 0.f;

    const int a_row0 = tid >> 4;
    const int a_c2 = tid & 15;
    const int b_row0 = tid >> 2;
    const int b_seg = tid & 3;

    // ldmatrix lane-address components
    const int grp = lane >> 3;          // 0..3
    const int lr = lane & 7;            // row within 8-row tile
    // A tile i, k-half from grp>>1, row-half from grp&1:
    const int a_lrow = (grp & 1) * 8 + lr;
    const int a_kadd = (grp >> 1) * 16;
    // B pair jj: n-tile from grp>>1, k-half from grp&1:
    const int b_kadd = (grp & 1) * 16;
    const int b_jadd = (grp >> 1) * 8 + lr;   // row within the 16-row j-pair

    float2 areg[2];

    auto loadA = [&](int kc) {
#pragma unroll
        for (int it = 0; it < 2; it++) {
            const int row = a_row0 + it * 32;
            const int gr = bm + row;
            areg[it] = make_float2(0.f, 0.f);
            if (gr < NN)
                areg[it] = *(const float2*)&A[(size_t)gr * DD + kc * BK + a_c2 * 2];
        }
    };
    auto storeA = [&](int buf) {
#pragma unroll
        for (int it = 0; it < 2; it++) {
            const int row = a_row0 + it * 32;
            float hx, hy;
            const uint32_t hi = pack_hi(areg[it].x, areg[it].y, hx, hy);
            const uint32_t lo = pack_lo(areg[it].x - hx, areg[it].y - hy);
            *(uint32_t*)(smem + A_HI(buf) + row * RS + a_c2 * 4) = hi;
            *(uint32_t*)(smem + A_LO(buf) + row * RS + a_c2 * 4) = lo;
        }
    };
    auto issueB = [&](int kc, int buf) {
#pragma unroll
        for (int it = 0; it < 4; it++) {
            const int row = b_row0 + it * 128;
            const size_t gsrc = (size_t)row * DD + kc * BK + b_seg * 8;
            const uint32_t doff = row * RS + b_seg * 16;
            cp16(sb + B_HI(buf) + doff, g_Whi + gsrc);
            cp16(sb + B_LO(buf) + doff, g_Wlo + gsrc);
        }
        cp_commit();
    };

    loadA(0);
    issueB(0, 0);
    storeA(0);
    cp_wait_all();
    __syncthreads();

    for (int kc = 0; kc < NCH; kc++) {
        const int cur = kc & 1;
        const int nxt = cur ^ 1;
        if (kc + 1 < NCH) {
            loadA(kc + 1);
            issueB(kc + 1, nxt);
        }

#pragma unroll
        for (int s = 0; s < 2; s++) {
            const int koff = s * 32;
            // ---- A fragments via ldmatrix.x4 (hi and lo) ----
            uint32_t ah[4][4], al[4][4];
#pragma unroll
            for (int i = 0; i < 4; i++) {
                const uint32_t aoff = (i * 16 + a_lrow) * RS + koff + a_kadd;
                ldm_x4(sb + A_HI(cur) + aoff, ah[i][0], ah[i][1], ah[i][2], ah[i][3]);
                ldm_x4(sb + A_LO(cur) + aoff, al[i][0], al[i][1], al[i][2], al[i][3]);
            }
            // ---- B fragments: one x4 covers two n-tiles (j, j+1) ----
            uint32_t bh[4][2], bl[4][2];
#pragma unroll
            for (int jj = 0; jj < 2; jj++) {
                const uint32_t boff =
                    (wid * 32 + jj * 16 + b_jadd) * RS + koff + b_kadd;
                ldm_x4(sb + B_HI(cur) + boff, bh[jj * 2][0], bh[jj * 2][1],
                       bh[jj * 2 + 1][0], bh[jj * 2 + 1][1]);
                ldm_x4(sb + B_LO(cur) + boff, bl[jj * 2][0], bl[jj * 2][1],
                       bl[jj * 2 + 1][0], bl[jj * 2 + 1][1]);
            }
#pragma unroll
            for (int j = 0; j < 4; j++) {
#pragma unroll
                for (int i = 0; i < 4; i++) {
                    mma16816(acc[i][j], ah[i], bh[j][0], bh[j][1]);
                    mma16816(acc[i][j], ah[i], bl[j][0], bl[j][1]);
                    mma16816(acc[i][j], al[i], bh[j][0], bh[j][1]);
                }
            }
        }

        if (kc + 1 < NCH) storeA(nxt);
        cp_wait_all();
        __syncthreads();
    }

    // ---- stage V tile [64 x 512] into smem (stride 516: conflict-free) ----
    const int g8 = lane >> 2;
    float* sV = (float*)smem;
#pragma unroll
    for (int i = 0; i < 4; i++) {
#pragma unroll
        for (int j = 0; j < 4; j++) {
            const int col = wid * 32 + j * 8 + t * 2;
            const int r0 = i * 16 + g8;
            const int r1 = r0 + 8;
            sV[r0 * VST + col] = acc[i][j][0];
            sV[r0 * VST + col + 1] = acc[i][j][1];
            sV[r1 * VST + col] = acc[i][j][2];
            sV[r1 * VST + col + 1] = acc[i][j][3];
        }
    }
    __syncthreads();

    // ---- dots: warp wid handles rows wid*4 .. wid*4+3 of this tile ----
    const float bconst = bptr[0];
#pragma unroll
    for (int rr = 0; rr < 4; rr++) {
        const int row = wid * 4 + rr;
        const int n = bm + row;
        if (n >= NN) break;

        const float4* __restrict__ v = (const float4*)(sV + row * VST);
        const float4* __restrict__ p = (const float4*)(hpl + (size_t)n * DD);
        const float4* __restrict__ g0 = (const float4*)(A + (size_t)samp[0 * NN + n] * DD);
        const float4* __restrict__ g1 = (const float4*)(A + (size_t)samp[1 * NN + n] * DD);
        const float4* __restrict__ g2 = (const float4*)(A + (size_t)samp[2 * NN + n] * DD);
        const float4* __restrict__ g3 = (const float4*)(A + (size_t)samp[3 * NN + n] * DD);

        float a0 = 0.f, a1 = 0.f, a2 = 0.f, a3 = 0.f, a4 = 0.f;
#pragma unroll
        for (int c = lane; c < DD / 4; c += 32) {
            const float4 vv = v[c];
            float4 x;
            x = p[c];  a0 += vv.x * x.x + vv.y * x.y + vv.z * x.z + vv.w * x.w;
            x = g0[c]; a1 += vv.x * x.x + vv.y * x.y + vv.z * x.z + vv.w * x.w;
            x = g1[c]; a2 += vv.x * x.x + vv.y * x.y + vv.z * x.z + vv.w * x.w;
            x = g2[c]; a3 += vv.x * x.x + vv.y * x.y + vv.z * x.z + vv.w * x.w;
            x = g3[c]; a4 += vv.x * x.x + vv.y * x.y + vv.z * x.z + vv.w * x.w;
        }
#pragma unroll
        for (int off = 16; off > 0; off >>= 1) {
            a0 += __shfl_xor_sync(0xFFFFFFFFu, a0, off);
            a1 += __shfl_xor_sync(0xFFFFFFFFu, a1, off);
            a2 += __shfl_xor_sync(0xFFFFFFFFu, a2, off);
            a3 += __shfl_xor_sync(0xFFFFFFFFu, a3, off);
            a4 += __shfl_xor_sync(0xFFFFFFFFu, a4, off);
        }
        if (lane == 0) {
            out[n] = a0 + bconst;
            const float r1 = a1 + bconst, r2 = a2 + bconst;
            const float r3 = a3 + bconst, r4 = a4 + bconst;
            out[NN + 0 * NN + n] = r1;  out[NN + (SS + 0) * NN + n] = r1;
            out[NN + 1 * NN + n] = r2;  out[NN + (SS + 1) * NN + n] = r2;
            out[NN + 2 * NN + n] = r3;  out[NN + (SS + 2) * NN + n] = r3;
            out[NN + 3 * NN + n] = r4;  out[NN + (SS + 3) * NN + n] = r4;
        }
    }
}

extern "C" void kernel_launch(void* const* d_in, const int* in_sizes, int n_in,
                              void* d_out, int out_size) {
    const float* h_c  = (const float*)d_in[0];
    const float* h_pl = (const float*)d_in[1];
    const int*   samp = (const int*)d_in[2];
    const float* W    = (const float*)d_in[3];
    const float* b    = (const float*)d_in[4];
    float* out = (float*)d_out;

    split_w<<<512, 256>>>(W);

    static int smem_set = 0;
    if (!smem_set) {
        cudaFuncSetAttribute(gemm_fused, cudaFuncAttributeMaxDynamicSharedMemorySize,
                             SMEM_BYTES);
        smem_set = 1;
    }
    const int grid = (NN + BM - 1) / BM;   // 1563
    gemm_fused<<<grid, 512, SMEM_BYTES>>>(h_c, h_pl, samp, b, out);
}